// round 13
// baseline (speedup 1.0000x reference)
#include <cuda_runtime.h>
#include <cuda_fp16.h>
#include <math.h>
#include <stdint.h>

#define NN 50000
#define NP 4
#define NE 800000
#define D 256
#define DH 128
#define NND (NN * D)
#define NROWS (NP * NN)
#define NG (NP * NN)              // total (path,node) rows = 200000
#define SCAN_BLK 391              // ceil(200000/512)

// ---------------- scratch (device globals; no allocation allowed) ----------
__device__ __half g_xh[NND];           // x in fp16 [50000][256]
__device__ __half g_wsT[NP * D * D];   // Ws transposed [p][n][k] fp16
__device__ __half g_w1T[DH * D];       // W1 transposed [n][k] fp16
__device__ __half g_xwh[NP * NND];     // x@W_p fp16 (pull-only)
__device__ __half g_zh[NP * NND];      // z interleaved [node][path][256] fp16
__device__ int   g_deg[NG];
__device__ float g_dinv[NG];
__device__ int   g_rowoff[NG + 1];
__device__ int   g_rowcur[NG];
__device__ int   g_srcs[NP * NE];
__device__ int   g_part[SCAN_BLK];

// ---------------- mma / ldmatrix / cp.async helpers -------------------------
__device__ __forceinline__ void mma_f16(float* d, const uint32_t* a,
                                        const uint32_t* b) {
    asm volatile(
        "mma.sync.aligned.m16n8k16.row.col.f32.f16.f16.f32 "
        "{%0,%1,%2,%3}, {%4,%5,%6,%7}, {%8,%9}, {%0,%1,%2,%3};\n"
        : "+f"(d[0]), "+f"(d[1]), "+f"(d[2]), "+f"(d[3])
        : "r"(a[0]), "r"(a[1]), "r"(a[2]), "r"(a[3]),
          "r"(b[0]), "r"(b[1]));
}

__device__ __forceinline__ void ldsm_x4(uint32_t& r0, uint32_t& r1,
                                        uint32_t& r2, uint32_t& r3,
                                        uint32_t addr) {
    asm volatile("ldmatrix.sync.aligned.m8n8.x4.shared.b16 {%0,%1,%2,%3}, [%4];"
                 : "=r"(r0), "=r"(r1), "=r"(r2), "=r"(r3) : "r"(addr));
}

__device__ __forceinline__ void cp16(uint32_t dst, const void* src, bool pred) {
    asm volatile("cp.async.cg.shared.global [%0], [%1], 16, %2;"
                 :: "r"(dst), "l"(src), "r"(pred ? 16 : 0) : "memory");
}
#define CP_COMMIT() asm volatile("cp.async.commit_group;" ::: "memory")

// smem geometry: pitch 20 uint32/row, 128 rows/stage, 4 stages
#define SPITCH 20
#define BUFBYTES (128 * SPITCH * 4)     // 10240 per stage per operand
#define MIBYTES  (16 * SPITCH * 4)      // 1280
#define NSTAGE 4
#define NTILES 8                        // K = 256, BK = 32
#define DYNBYTES (2 * NSTAGE * BUFBYTES)  // 81920

// ---------------- prep: fp32 -> fp16 conversions ---------------------------
__global__ void k_cvt_x(const float* __restrict__ x) {
    int i = blockIdx.x * 256 + threadIdx.x;      // over float4s
    if (i < NND / 4) {
        float4 v = ((const float4*)x)[i];
        __half2* o = (__half2*)g_xh + i * 2;
        o[0] = __floats2half2_rn(v.x, v.y);
        o[1] = __floats2half2_rn(v.z, v.w);
    }
}

// transpose [z][K][N] fp32 -> [z][N][K] fp16 (K,N multiples of 32)
__global__ void k_cvt_wT(const float* __restrict__ in, __half* __restrict__ out,
                         int K, int N) {
    __shared__ float t[32][33];
    int z = blockIdx.z;
    int k0 = blockIdx.x * 32, n0 = blockIdx.y * 32;
    int tx = threadIdx.x, ty = threadIdx.y;      // 32 x 8
    const float* ip = in + (size_t)z * K * N;
    __half* op = out + (size_t)z * K * N;
#pragma unroll
    for (int j = 0; j < 32; j += 8)
        t[ty + j][tx] = ip[(size_t)(k0 + ty + j) * N + n0 + tx];
    __syncthreads();
#pragma unroll
    for (int j = 0; j < 32; j += 8)
        op[(size_t)(n0 + ty + j) * K + k0 + tx] = __float2half(t[tx][ty + j]);
}

// mainloop body (shared by both GEMMs): 4-stage ring, one sync per tile.
#define GEMM_MAINLOOP()                                                        \
    _Pragma("unroll")                                                          \
    for (int s = 0; s < NSTAGE - 1; s++) {                                     \
        const __half* Ap2 = Ap + s * 32;                                       \
        const __half* Bp2 = Bp + s * 32;                                       \
        cp16(aDstB + s * BUFBYTES, Ap2, aval);                                 \
        cp16(aDstB + s * BUFBYTES + 16, Ap2 + 8, aval);                        \
        cp16(bDstB + s * BUFBYTES, Bp2, true);                                 \
        cp16(bDstB + s * BUFBYTES + 16, Bp2 + 8, true);                        \
        CP_COMMIT();                                                           \
    }                                                                          \
    _Pragma("unroll")                                                          \
    for (int t = 0; t < NTILES; t++) {                                         \
        if (t < NTILES - 2)                                                    \
            asm volatile("cp.async.wait_group 2;" ::: "memory");               \
        else if (t == NTILES - 2)                                              \
            asm volatile("cp.async.wait_group 1;" ::: "memory");               \
        else                                                                   \
            asm volatile("cp.async.wait_group 0;" ::: "memory");               \
        __syncthreads();                                                       \
        if (t + NSTAGE - 1 < NTILES) {                                         \
            const int ws = (t + NSTAGE - 1) & (NSTAGE - 1);                    \
            const __half* Ap2 = Ap + (t + NSTAGE - 1) * 32;                    \
            const __half* Bp2 = Bp + (t + NSTAGE - 1) * 32;                    \
            cp16(aDstB + ws * BUFBYTES, Ap2, aval);                            \
            cp16(aDstB + ws * BUFBYTES + 16, Ap2 + 8, aval);                   \
            cp16(bDstB + ws * BUFBYTES, Bp2, true);                            \
            cp16(bDstB + ws * BUFBYTES + 16, Bp2 + 8, true);                   \
            CP_COMMIT();                                                       \
        }                                                                      \
        const int slot = t & (NSTAGE - 1);                                     \
        _Pragma("unroll")                                                      \
        for (int ks = 0; ks < 2; ks++) {                                       \
            uint32_t afr[4][4], bfr[4][2];                                     \
            const uint32_t ao = aAddrB + slot * BUFBYTES + ks * 32;            \
            const uint32_t bo = bAddrB + slot * BUFBYTES + ks * 32;            \
            _Pragma("unroll")                                                  \
            for (int mi = 0; mi < 4; mi++)                                     \
                ldsm_x4(afr[mi][0], afr[mi][1], afr[mi][2], afr[mi][3],        \
                        ao + mi * MIBYTES);                                    \
            ldsm_x4(bfr[0][0], bfr[0][1], bfr[1][0], bfr[1][1], bo);           \
            ldsm_x4(bfr[2][0], bfr[2][1], bfr[3][0], bfr[3][1], bo + MIBYTES); \
            _Pragma("unroll")                                                  \
            for (int mi = 0; mi < 4; mi++)                                     \
                _Pragma("unroll")                                              \
                for (int ni = 0; ni < 4; ni++)                                 \
                    mma_f16(acc[mi][ni], afr[mi], bfr[ni]);                    \
        }                                                                      \
    }

// ---- GEMM1 (per path): xw = xh @ WsT^T (fp16 in, half out). 128x128 -------
__global__ void __launch_bounds__(256, 2) k_gemm_xw(
    const __half* __restrict__ A, const __half* __restrict__ B,
    __half* __restrict__ C, int M, int N)
{
    const int K = 256;
    extern __shared__ uint32_t dynSmem[];

    const int tid  = threadIdx.x;
    const int lane = tid & 31;
    const int warp = tid >> 5;
    const int wm = warp & 1;
    const int wn = warp >> 1;
    const int grp = lane >> 2;
    const int tig = lane & 3;
    const int bm = blockIdx.y * 128;
    const int bn = blockIdx.x * 128;

    const int lrow = tid >> 1;               // 0..127
    const int lkc  = (tid & 1) * 8;          // half2 base 0 or 8
    const bool aval = (bm + lrow) < M;
    const __half* Ap = A + (long long)(bm + lrow) * K + lkc * 2;
    const __half* Bp = B + (long long)(bn + lrow) * K + lkc * 2;

    const uint32_t asBase = (uint32_t)__cvta_generic_to_shared(dynSmem);
    const uint32_t bsBase = asBase + NSTAGE * BUFBYTES;
    const uint32_t aDstB = asBase + ((lrow * SPITCH + lkc) << 2);
    const uint32_t bDstB = bsBase + ((lrow * SPITCH + lkc) << 2);
    const uint32_t aAddrB = asBase +
        (((wm * 64 + (lane & 15)) * SPITCH + (lane >> 4) * 4) << 2);
    const uint32_t bAddrB = bsBase +
        (((wn * 32 + ((lane >> 4) << 3) + (lane & 7)) * SPITCH
          + ((lane >> 3) & 1) * 4) << 2);

    float acc[4][4][4] = {};

    GEMM_MAINLOOP()

#pragma unroll
    for (int mi = 0; mi < 4; mi++) {
        const int r0 = bm + wm * 64 + mi * 16 + grp;
#pragma unroll
        for (int ni = 0; ni < 4; ni++) {
            const int c0 = bn + wn * 32 + ni * 8 + 2 * tig;
            if (r0 < M)
                *(__half2*)&C[(long long)r0 * N + c0] =
                    __floats2half2_rn(acc[mi][ni][0], acc[mi][ni][1]);
            if (r0 + 8 < M)
                *(__half2*)&C[(long long)(r0 + 8) * N + c0] =
                    __floats2half2_rn(acc[mi][ni][2], acc[mi][ni][3]);
        }
    }
}

// ---- GEMM2 fully fused: logits + softmax + combine ------------------------
// A = g_zh fp16 (rows g = node*4 + p), B = g_w1T fp16 [128][256] k-major.
__global__ void __launch_bounds__(256, 2) k_gemm_attn(
    const __half* __restrict__ A, const __half* __restrict__ B,
    const float* __restrict__ b1v, const float* __restrict__ w2v,
    float* __restrict__ out, int M)
{
    const int K = 256;
    extern __shared__ uint32_t dynSmem[];
    __shared__ float rowsum[128];
    __shared__ float w2s[128];
    __shared__ float b1s[128];

    const int tid  = threadIdx.x;
    const int lane = tid & 31;
    const int warp = tid >> 5;
    const int wm = warp & 1;
    const int wn = warp >> 1;
    const int grp = lane >> 2;
    const int tig = lane & 3;
    const int bm = blockIdx.y * 128;

    const int lrow = tid >> 1;
    const int lkc  = (tid & 1) * 8;
    const bool aval = (bm + lrow) < M;
    const __half* Ap = A + (long long)(bm + lrow) * K + lkc * 2;
    const __half* Bp = B + (long long)lrow * K + lkc * 2;   // N=128 rows

    const uint32_t asBase = (uint32_t)__cvta_generic_to_shared(dynSmem);
    const uint32_t bsBase = asBase + NSTAGE * BUFBYTES;
    const uint32_t aDstB = asBase + ((lrow * SPITCH + lkc) << 2);
    const uint32_t bDstB = bsBase + ((lrow * SPITCH + lkc) << 2);
    const uint32_t aAddrB = asBase +
        (((wm * 64 + (lane & 15)) * SPITCH + (lane >> 4) * 4) << 2);
    const uint32_t bAddrB = bsBase +
        (((wn * 32 + ((lane >> 4) << 3) + (lane & 7)) * SPITCH
          + ((lane >> 3) & 1) * 4) << 2);

    float acc[4][4][4] = {};

    if (tid < 128) { rowsum[tid] = 0.f; w2s[tid] = w2v[tid]; b1s[tid] = b1v[tid]; }

    GEMM_MAINLOOP()

    // ---- logits: tanh(acc + b1) . w2, reduced per row ----
#pragma unroll
    for (int mi = 0; mi < 4; mi++) {
        float p0 = 0.f, p1 = 0.f;
#pragma unroll
        for (int ni = 0; ni < 4; ni++) {
            const int c0 = wn * 32 + ni * 8 + 2 * tig;
            float t;
            t = tanhf(acc[mi][ni][0] + b1s[c0]);     p0 += t * w2s[c0];
            t = tanhf(acc[mi][ni][1] + b1s[c0 + 1]); p0 += t * w2s[c0 + 1];
            t = tanhf(acc[mi][ni][2] + b1s[c0]);     p1 += t * w2s[c0];
            t = tanhf(acc[mi][ni][3] + b1s[c0 + 1]); p1 += t * w2s[c0 + 1];
        }
        p0 += __shfl_xor_sync(0xffffffffu, p0, 1);
        p0 += __shfl_xor_sync(0xffffffffu, p0, 2);
        p1 += __shfl_xor_sync(0xffffffffu, p1, 1);
        p1 += __shfl_xor_sync(0xffffffffu, p1, 2);
        if (tig == 0) {
            atomicAdd(&rowsum[wm * 64 + mi * 16 + grp], p0);
            atomicAdd(&rowsum[wm * 64 + mi * 16 + grp + 8], p1);
        }
    }
    __syncthreads();

    // ---- per-node softmax over the 4 paths ----
    int nib = (M - bm) >> 2;
    const int nodes_in_blk = nib < 32 ? nib : 32;
    if (tid < 32 && tid < nodes_in_blk) {
        float l0 = rowsum[tid * 4], l1 = rowsum[tid * 4 + 1];
        float l2 = rowsum[tid * 4 + 2], l3 = rowsum[tid * 4 + 3];
        float m = fmaxf(fmaxf(l0, l1), fmaxf(l2, l3));
        float e0 = __expf(l0 - m), e1 = __expf(l1 - m);
        float e2 = __expf(l2 - m), e3 = __expf(l3 - m);
        float inv = 1.0f / (e0 + e1 + e2 + e3);
        rowsum[tid * 4]     = e0 * inv;
        rowsum[tid * 4 + 1] = e1 * inv;
        rowsum[tid * 4 + 2] = e2 * inv;
        rowsum[tid * 4 + 3] = e3 * inv;
    }
    __syncthreads();

    // ---- combine: out[node][d] = sum_p beta * z (z tile hot in L2) ----
    const int node0 = bm >> 2;
#pragma unroll
    for (int i = 0; i < 32; i++) {
        int idx = tid + 256 * i;
        int nl = idx >> 8;
        int dd = idx & 255;
        if (nl >= nodes_in_blk) break;
        const __half* zr = A + (long long)(bm + nl * 4) * K + dd;
        float v = rowsum[nl * 4]     * __half2float(zr[0])
                + rowsum[nl * 4 + 1] * __half2float(zr[K])
                + rowsum[nl * 4 + 2] * __half2float(zr[2 * K])
                + rowsum[nl * 4 + 3] * __half2float(zr[3 * K]);
        out[(long long)(node0 + nl) * D + dd] = v;
    }
}

// ---------------- GCN aggregation pipeline (all 4 paths batched) -----------
__global__ void k_deg_init() {
    int i = blockIdx.x * 256 + threadIdx.x;
    if (i < NG) g_deg[i] = 1;   // self loop
}

__global__ void k_hist(const int* __restrict__ eidx) {
    int e = blockIdx.x * 256 + threadIdx.x;
    if (e < NP * NE) {
        int p = e / NE, i = e - p * NE;
        int dst = eidx[(size_t)p * 2 * NE + NE + i];
        atomicAdd(&g_deg[p * NN + dst], 1);
    }
}

__global__ void k_scan1() {
    __shared__ int red[8];
    int b = blockIdx.x, tid = threadIdx.x;
    int lane = tid & 31, warp = tid >> 5;
    int i0 = b * 512 + tid * 2;
    int s = 0;
    if (i0 < NG)     s += g_deg[i0] - 1;
    if (i0 + 1 < NG) s += g_deg[i0 + 1] - 1;
#pragma unroll
    for (int o = 16; o; o >>= 1) s += __shfl_xor_sync(0xffffffffu, s, o);
    if (lane == 0) red[warp] = s;
    __syncthreads();
    if (tid == 0) {
        int t = 0;
#pragma unroll
        for (int w = 0; w < 8; w++) t += red[w];
        g_part[b] = t;
    }
}

__global__ void k_scan2() {
    __shared__ int s[512];
    int tid = threadIdx.x;
    int v = (tid < SCAN_BLK) ? g_part[tid] : 0;
    s[tid] = v;
    __syncthreads();
    for (int off = 1; off < 512; off <<= 1) {
        int u = (tid >= off) ? s[tid - off] : 0;
        __syncthreads();
        s[tid] += u;
        __syncthreads();
    }
    if (tid < SCAN_BLK) g_part[tid] = s[tid] - v;   // exclusive
}

__global__ void k_scan3() {
    __shared__ int wsum[8];
    int b = blockIdx.x, tid = threadIdx.x;
    int lane = tid & 31, warp = tid >> 5;
    int i0 = b * 512 + tid * 2;
    int d0 = (i0 < NG) ? g_deg[i0] : 1;
    int d1 = (i0 + 1 < NG) ? g_deg[i0 + 1] : 1;
    int v0 = d0 - 1, v1 = d1 - 1;
    int s = v0 + v1;
    int sc = s;
#pragma unroll
    for (int o = 1; o < 32; o <<= 1) {
        int u = __shfl_up_sync(0xffffffffu, sc, o);
        if (lane >= o) sc += u;
    }
    if (lane == 31) wsum[warp] = sc;
    __syncthreads();
    int wbase = 0;
    for (int w = 0; w < warp; w++) wbase += wsum[w];
    int base = g_part[b] + wbase + (sc - s);
    if (i0 < NG) {
        g_rowoff[i0] = base; g_rowcur[i0] = base;
        g_dinv[i0] = rsqrtf((float)d0);
    }
    if (i0 + 1 < NG) {
        g_rowoff[i0 + 1] = base + v0; g_rowcur[i0 + 1] = base + v0;
        g_dinv[i0 + 1] = rsqrtf((float)d1);
    }
    if (b == 0 && tid == 0) g_rowoff[NG] = NP * NE;
}

__global__ void k_fill(const int* __restrict__ eidx) {
    int e = blockIdx.x * 256 + threadIdx.x;
    if (e < NP * NE) {
        int p = e / NE, i = e - p * NE;
        int src = eidx[(size_t)p * 2 * NE + i];
        int dst = eidx[(size_t)p * 2 * NE + NE + i];
        int pos = atomicAdd(&g_rowcur[p * NN + dst], 1);
        g_srcs[pos] = src;
    }
}

// pull (per path): one warp per node; LDG.128 gather, 8-edge unroll, fp32
// acc. z written INTERLEAVED row (node*4 + p).
__global__ void k_pull(const float* __restrict__ bs, int p) {
    int node = blockIdx.x * 8 + (threadIdx.x >> 5);
    if (node >= NN) return;
    int lane = threadIdx.x & 31;
    int g = p * NN + node;

    float di = g_dinv[g];
    const uint4* xw = (const uint4*)g_xwh + (size_t)p * (NND / 8);
    float acc[8];
    {
        uint4 v = xw[(size_t)node * 32 + lane];
        const __half2* h = (const __half2*)&v;
        float dd = di * di;
#pragma unroll
        for (int j = 0; j < 4; j++) {
            float2 f = __half22float2(h[j]);
            acc[2 * j]     = dd * f.x;
            acc[2 * j + 1] = dd * f.y;
        }
    }

    int beg = g_rowoff[g];
    int end = g_rowoff[g + 1];
    const float* dv = g_dinv + p * NN;
    int e = beg;
    for (; e + 8 <= end; e += 8) {
        int   si[8];
        float nr[8];
        uint4 vv[8];
#pragma unroll
        for (int q = 0; q < 8; q++) si[q] = g_srcs[e + q];
#pragma unroll
        for (int q = 0; q < 8; q++) nr[q] = di * dv[si[q]];
#pragma unroll
        for (int q = 0; q < 8; q++) vv[q] = xw[(size_t)si[q] * 32 + lane];
#pragma unroll
        for (int j = 0; j < 4; j++) {
#pragma unroll
            for (int q = 0; q < 8; q++) {
                float2 f = __half22float2(((const __half2*)&vv[q])[j]);
                acc[2 * j]     = fmaf(nr[q], f.x, acc[2 * j]);
                acc[2 * j + 1] = fmaf(nr[q], f.y, acc[2 * j + 1]);
            }
        }
    }
    for (; e < end; e++) {
        int s0 = g_srcs[e];
        float n0 = di * dv[s0];
        uint4 v0 = xw[(size_t)s0 * 32 + lane];
        const __half2* h0 = (const __half2*)&v0;
#pragma unroll
        for (int j = 0; j < 4; j++) {
            float2 f0 = __half22float2(h0[j]);
            acc[2 * j]     = fmaf(n0, f0.x, acc[2 * j]);
            acc[2 * j + 1] = fmaf(n0, f0.y, acc[2 * j + 1]);
        }
    }

    // write: lane owns dims [lane*8, lane*8+8)
    int c = lane * 8;
    const float4* bp4 = (const float4*)(bs + p * D + c);
    float4 b0 = bp4[0], b1 = bp4[1];
    uint4 o;
    __half2* oh = (__half2*)&o;
    oh[0] = __floats2half2_rn(acc[0] + b0.x, acc[1] + b0.y);
    oh[1] = __floats2half2_rn(acc[2] + b0.z, acc[3] + b0.w);
    oh[2] = __floats2half2_rn(acc[4] + b1.x, acc[5] + b1.y);
    oh[3] = __floats2half2_rn(acc[6] + b1.z, acc[7] + b1.w);
    ((uint4*)g_zh)[((size_t)node * NP + p) * 32 + lane] = o;
}

// ---------------- launch ----------------------------------------------------
extern "C" void kernel_launch(void* const* d_in, const int* in_sizes, int n_in,
                              void* d_out, int out_size) {
    const float* x    = (const float*)d_in[0];
    const int*   eidx = (const int*)d_in[1];
    const float* Ws   = (const float*)d_in[2];
    const float* bs   = (const float*)d_in[3];
    const float* w1   = (const float*)d_in[4];
    const float* b1   = (const float*)d_in[5];
    const float* w2   = (const float*)d_in[6];
    float* out = (float*)d_out;

    void* p_xh = nullptr; void* p_wsT = nullptr; void* p_w1T = nullptr;
    void* p_xwh = nullptr; void* p_zh = nullptr;
    cudaGetSymbolAddress(&p_xh,  g_xh);
    cudaGetSymbolAddress(&p_wsT, g_wsT);
    cudaGetSymbolAddress(&p_w1T, g_w1T);
    cudaGetSymbolAddress(&p_xwh, g_xwh);
    cudaGetSymbolAddress(&p_zh,  g_zh);

    cudaFuncSetAttribute(k_gemm_xw,
        cudaFuncAttributeMaxDynamicSharedMemorySize, DYNBYTES);
    cudaFuncSetAttribute(k_gemm_attn,
        cudaFuncAttributeMaxDynamicSharedMemorySize, DYNBYTES);

    // one-time side stream + events (no device memory; identical launches
    // every call)
    static cudaStream_t s_side = nullptr;
    static cudaEvent_t  s_fork = nullptr, s_join = nullptr;
    static cudaEvent_t  s_evG[NP] = {nullptr, nullptr, nullptr, nullptr};
    if (s_side == nullptr) {
        cudaStreamCreateWithFlags(&s_side, cudaStreamNonBlocking);
        cudaEventCreateWithFlags(&s_fork, cudaEventDisableTiming);
        cudaEventCreateWithFlags(&s_join, cudaEventDisableTiming);
        for (int p = 0; p < NP; p++)
            cudaEventCreateWithFlags(&s_evG[p], cudaEventDisableTiming);
    }

    // ---- fork: CSR build (depends only on eidx) on side stream ----
    cudaEventRecord(s_fork, 0);
    cudaStreamWaitEvent(s_side, s_fork, 0);
    k_deg_init<<<(NG + 255) / 256, 256, 0, s_side>>>();
    k_hist<<<(NP * NE + 255) / 256, 256, 0, s_side>>>(eidx);
    k_scan1<<<SCAN_BLK, 256, 0, s_side>>>();
    k_scan2<<<1, 512, 0, s_side>>>();
    k_scan3<<<SCAN_BLK, 256, 0, s_side>>>();
    k_fill<<<(NP * NE + 255) / 256, 256, 0, s_side>>>(eidx);

    // ---- main: fp16 prep + per-path feature GEMMs (event per path) ----
    k_cvt_x<<<(NND / 4 + 255) / 256, 256>>>(x);
    k_cvt_wT<<<dim3(D / 32, D / 32, NP), dim3(32, 8)>>>(Ws, (__half*)p_wsT, D, D);
    k_cvt_wT<<<dim3(D / 32, DH / 32, 1), dim3(32, 8)>>>(w1, (__half*)p_w1T, D, DH);
    for (int p = 0; p < NP; p++) {
        k_gemm_xw<<<dim3(D / 128, (NN + 127) / 128), 256, DYNBYTES>>>(
            (const __half*)p_xh, (const __half*)p_wsT + (size_t)p * D * D,
            (__half*)p_xwh + (size_t)p * NND, NN, D);
        cudaEventRecord(s_evG[p], 0);
    }

    // ---- side: per-path pull as soon as its GEMM (and CSR) is done ----
    for (int p = 0; p < NP; p++) {
        cudaStreamWaitEvent(s_side, s_evG[p], 0);
        k_pull<<<(NN + 7) / 8, 256, 0, s_side>>>(bs, p);
    }
    cudaEventRecord(s_join, s_side);

    // ---- main: fused logits + softmax + combine after all pulls ----
    cudaStreamWaitEvent(0, s_join, 0);
    k_gemm_attn<<<dim3(1, (NROWS + 127) / 128), 256, DYNBYTES>>>(
        (const __half*)p_zh, (const __half*)p_w1T, b1, w2, out, NROWS);
}

// round 14
// speedup vs baseline: 1.1048x; 1.1048x over previous
#include <cuda_runtime.h>
#include <cuda_fp16.h>
#include <math.h>
#include <stdint.h>

#define NN 50000
#define NP 4
#define NE 800000
#define D 256
#define DH 128
#define NND (NN * D)
#define NROWS (NP * NN)
#define NG (NP * NN)              // total (path,node) rows = 200000
#define SCAN_BLK 391              // ceil(200000/512)

// ---------------- scratch (device globals; no allocation allowed) ----------
__device__ __half g_xh[NND];           // x in fp16 [50000][256]
__device__ __half g_wsT[NP * D * D];   // Ws transposed [p][n][k] fp16
__device__ __half g_w1T[DH * D];       // W1 transposed [n][k] fp16
__device__ __half g_xwh[NP * NND];     // x@W_p fp16 (pull-only)
__device__ __half g_zh[NP * NND];      // z interleaved [node][path][256] fp16
__device__ int   g_deg[NG];
__device__ float g_dinv[NG];
__device__ int   g_rowoff[NG + 1];
__device__ int   g_rowcur[NG];
__device__ int   g_srcs[NP * NE];
__device__ int   g_part[SCAN_BLK];

// ---------------- mma / ldmatrix / cp.async helpers -------------------------
__device__ __forceinline__ void mma_f16(float* d, const uint32_t* a,
                                        const uint32_t* b) {
    asm volatile(
        "mma.sync.aligned.m16n8k16.row.col.f32.f16.f16.f32 "
        "{%0,%1,%2,%3}, {%4,%5,%6,%7}, {%8,%9}, {%0,%1,%2,%3};\n"
        : "+f"(d[0]), "+f"(d[1]), "+f"(d[2]), "+f"(d[3])
        : "r"(a[0]), "r"(a[1]), "r"(a[2]), "r"(a[3]),
          "r"(b[0]), "r"(b[1]));
}

__device__ __forceinline__ void ldsm_x4(uint32_t& r0, uint32_t& r1,
                                        uint32_t& r2, uint32_t& r3,
                                        uint32_t addr) {
    asm volatile("ldmatrix.sync.aligned.m8n8.x4.shared.b16 {%0,%1,%2,%3}, [%4];"
                 : "=r"(r0), "=r"(r1), "=r"(r2), "=r"(r3) : "r"(addr));
}

__device__ __forceinline__ void cp16(uint32_t dst, const void* src, bool pred) {
    asm volatile("cp.async.cg.shared.global [%0], [%1], 16, %2;"
                 :: "r"(dst), "l"(src), "r"(pred ? 16 : 0) : "memory");
}
#define CP_COMMIT() asm volatile("cp.async.commit_group;" ::: "memory")

// smem geometry: pitch 20 uint32/row, 128 rows/stage, 4 stages
#define SPITCH 20
#define BUFBYTES (128 * SPITCH * 4)     // 10240 per stage per operand
#define MIBYTES  (16 * SPITCH * 4)      // 1280
#define NSTAGE 4
#define NTILES 8                        // K = 256, BK = 32
#define DYNBYTES (2 * NSTAGE * BUFBYTES)  // 81920

// ---------------- prep: fp32 -> fp16 conversions ---------------------------
__global__ void k_cvt_x(const float* __restrict__ x) {
    int i = blockIdx.x * 256 + threadIdx.x;      // over float4s
    if (i < NND / 4) {
        float4 v = ((const float4*)x)[i];
        __half2* o = (__half2*)g_xh + i * 2;
        o[0] = __floats2half2_rn(v.x, v.y);
        o[1] = __floats2half2_rn(v.z, v.w);
    }
}

// transpose [z][K][N] fp32 -> [z][N][K] fp16 (K,N multiples of 32)
__global__ void k_cvt_wT(const float* __restrict__ in, __half* __restrict__ out,
                         int K, int N) {
    __shared__ float t[32][33];
    int z = blockIdx.z;
    int k0 = blockIdx.x * 32, n0 = blockIdx.y * 32;
    int tx = threadIdx.x, ty = threadIdx.y;      // 32 x 8
    const float* ip = in + (size_t)z * K * N;
    __half* op = out + (size_t)z * K * N;
#pragma unroll
    for (int j = 0; j < 32; j += 8)
        t[ty + j][tx] = ip[(size_t)(k0 + ty + j) * N + n0 + tx];
    __syncthreads();
#pragma unroll
    for (int j = 0; j < 32; j += 8)
        op[(size_t)(n0 + ty + j) * K + k0 + tx] = __float2half(t[tx][ty + j]);
}

// mainloop body (shared by both GEMMs): 4-stage ring, one sync per tile.
#define GEMM_MAINLOOP()                                                        \
    _Pragma("unroll")                                                          \
    for (int s = 0; s < NSTAGE - 1; s++) {                                     \
        const __half* Ap2 = Ap + s * 32;                                       \
        const __half* Bp2 = Bp + s * 32;                                       \
        cp16(aDstB + s * BUFBYTES, Ap2, aval);                                 \
        cp16(aDstB + s * BUFBYTES + 16, Ap2 + 8, aval);                        \
        cp16(bDstB + s * BUFBYTES, Bp2, true);                                 \
        cp16(bDstB + s * BUFBYTES + 16, Bp2 + 8, true);                        \
        CP_COMMIT();                                                           \
    }                                                                          \
    _Pragma("unroll")                                                          \
    for (int t = 0; t < NTILES; t++) {                                         \
        if (t < NTILES - 2)                                                    \
            asm volatile("cp.async.wait_group 2;" ::: "memory");               \
        else if (t == NTILES - 2)                                              \
            asm volatile("cp.async.wait_group 1;" ::: "memory");               \
        else                                                                   \
            asm volatile("cp.async.wait_group 0;" ::: "memory");               \
        __syncthreads();                                                       \
        if (t + NSTAGE - 1 < NTILES) {                                         \
            const int ws = (t + NSTAGE - 1) & (NSTAGE - 1);                    \
            const __half* Ap2 = Ap + (t + NSTAGE - 1) * 32;                    \
            const __half* Bp2 = Bp + (t + NSTAGE - 1) * 32;                    \
            cp16(aDstB + ws * BUFBYTES, Ap2, aval);                            \
            cp16(aDstB + ws * BUFBYTES + 16, Ap2 + 8, aval);                   \
            cp16(bDstB + ws * BUFBYTES, Bp2, true);                            \
            cp16(bDstB + ws * BUFBYTES + 16, Bp2 + 8, true);                   \
            CP_COMMIT();                                                       \
        }                                                                      \
        const int slot = t & (NSTAGE - 1);                                     \
        _Pragma("unroll")                                                      \
        for (int ks = 0; ks < 2; ks++) {                                       \
            uint32_t afr[4][4], bfr[4][2];                                     \
            const uint32_t ao = aAddrB + slot * BUFBYTES + ks * 32;            \
            const uint32_t bo = bAddrB + slot * BUFBYTES + ks * 32;            \
            _Pragma("unroll")                                                  \
            for (int mi = 0; mi < 4; mi++)                                     \
                ldsm_x4(afr[mi][0], afr[mi][1], afr[mi][2], afr[mi][3],        \
                        ao + mi * MIBYTES);                                    \
            ldsm_x4(bfr[0][0], bfr[0][1], bfr[1][0], bfr[1][1], bo);           \
            ldsm_x4(bfr[2][0], bfr[2][1], bfr[3][0], bfr[3][1], bo + MIBYTES); \
            _Pragma("unroll")                                                  \
            for (int mi = 0; mi < 4; mi++)                                     \
                _Pragma("unroll")                                              \
                for (int ni = 0; ni < 4; ni++)                                 \
                    mma_f16(acc[mi][ni], afr[mi], bfr[ni]);                    \
        }                                                                      \
    }

// ---- GEMM1: xw[p] = xh @ WsT[p]^T (fp16 in, half out). 128x128, BK=32 -----
__global__ void __launch_bounds__(256, 2) k_gemm_xw(
    const __half* __restrict__ A, const __half* __restrict__ B,
    __half* __restrict__ C, int M, int N, long long sB, long long sC)
{
    const int K = 256;
    B += (long long)blockIdx.z * sB;
    C += (long long)blockIdx.z * sC;

    extern __shared__ uint32_t dynSmem[];

    const int tid  = threadIdx.x;
    const int lane = tid & 31;
    const int warp = tid >> 5;
    const int wm = warp & 1;
    const int wn = warp >> 1;
    const int grp = lane >> 2;
    const int tig = lane & 3;
    const int bm = blockIdx.y * 128;
    const int bn = blockIdx.x * 128;

    const int lrow = tid >> 1;               // 0..127
    const int lkc  = (tid & 1) * 8;          // half2 base 0 or 8
    const bool aval = (bm + lrow) < M;
    const __half* Ap = A + (long long)(bm + lrow) * K + lkc * 2;
    const __half* Bp = B + (long long)(bn + lrow) * K + lkc * 2;

    const uint32_t asBase = (uint32_t)__cvta_generic_to_shared(dynSmem);
    const uint32_t bsBase = asBase + NSTAGE * BUFBYTES;
    const uint32_t aDstB = asBase + ((lrow * SPITCH + lkc) << 2);
    const uint32_t bDstB = bsBase + ((lrow * SPITCH + lkc) << 2);
    const uint32_t aAddrB = asBase +
        (((wm * 64 + (lane & 15)) * SPITCH + (lane >> 4) * 4) << 2);
    const uint32_t bAddrB = bsBase +
        (((wn * 32 + ((lane >> 4) << 3) + (lane & 7)) * SPITCH
          + ((lane >> 3) & 1) * 4) << 2);

    float acc[4][4][4] = {};

    GEMM_MAINLOOP()

#pragma unroll
    for (int mi = 0; mi < 4; mi++) {
        const int r0 = bm + wm * 64 + mi * 16 + grp;
#pragma unroll
        for (int ni = 0; ni < 4; ni++) {
            const int c0 = bn + wn * 32 + ni * 8 + 2 * tig;
            if (r0 < M)
                *(__half2*)&C[(long long)r0 * N + c0] =
                    __floats2half2_rn(acc[mi][ni][0], acc[mi][ni][1]);
            if (r0 + 8 < M)
                *(__half2*)&C[(long long)(r0 + 8) * N + c0] =
                    __floats2half2_rn(acc[mi][ni][2], acc[mi][ni][3]);
        }
    }
}

// ---- GEMM2 fully fused: logits + softmax + combine ------------------------
// A = g_zh fp16 (rows g = node*4 + p), B = g_w1T fp16 [128][256] k-major.
__global__ void __launch_bounds__(256, 2) k_gemm_attn(
    const __half* __restrict__ A, const __half* __restrict__ B,
    const float* __restrict__ b1v, const float* __restrict__ w2v,
    float* __restrict__ out, int M)
{
    const int K = 256;
    extern __shared__ uint32_t dynSmem[];
    __shared__ float rowsum[128];
    __shared__ float w2s[128];
    __shared__ float b1s[128];

    const int tid  = threadIdx.x;
    const int lane = tid & 31;
    const int warp = tid >> 5;
    const int wm = warp & 1;
    const int wn = warp >> 1;
    const int grp = lane >> 2;
    const int tig = lane & 3;
    const int bm = blockIdx.y * 128;

    const int lrow = tid >> 1;
    const int lkc  = (tid & 1) * 8;
    const bool aval = (bm + lrow) < M;
    const __half* Ap = A + (long long)(bm + lrow) * K + lkc * 2;
    const __half* Bp = B + (long long)lrow * K + lkc * 2;   // N=128 rows

    const uint32_t asBase = (uint32_t)__cvta_generic_to_shared(dynSmem);
    const uint32_t bsBase = asBase + NSTAGE * BUFBYTES;
    const uint32_t aDstB = asBase + ((lrow * SPITCH + lkc) << 2);
    const uint32_t bDstB = bsBase + ((lrow * SPITCH + lkc) << 2);
    const uint32_t aAddrB = asBase +
        (((wm * 64 + (lane & 15)) * SPITCH + (lane >> 4) * 4) << 2);
    const uint32_t bAddrB = bsBase +
        (((wn * 32 + ((lane >> 4) << 3) + (lane & 7)) * SPITCH
          + ((lane >> 3) & 1) * 4) << 2);

    float acc[4][4][4] = {};

    if (tid < 128) { rowsum[tid] = 0.f; w2s[tid] = w2v[tid]; b1s[tid] = b1v[tid]; }

    GEMM_MAINLOOP()

    // ---- logits: tanh(acc + b1) . w2, reduced per row ----
#pragma unroll
    for (int mi = 0; mi < 4; mi++) {
        float p0 = 0.f, p1 = 0.f;
#pragma unroll
        for (int ni = 0; ni < 4; ni++) {
            const int c0 = wn * 32 + ni * 8 + 2 * tig;
            float t;
            t = tanhf(acc[mi][ni][0] + b1s[c0]);     p0 += t * w2s[c0];
            t = tanhf(acc[mi][ni][1] + b1s[c0 + 1]); p0 += t * w2s[c0 + 1];
            t = tanhf(acc[mi][ni][2] + b1s[c0]);     p1 += t * w2s[c0];
            t = tanhf(acc[mi][ni][3] + b1s[c0 + 1]); p1 += t * w2s[c0 + 1];
        }
        p0 += __shfl_xor_sync(0xffffffffu, p0, 1);
        p0 += __shfl_xor_sync(0xffffffffu, p0, 2);
        p1 += __shfl_xor_sync(0xffffffffu, p1, 1);
        p1 += __shfl_xor_sync(0xffffffffu, p1, 2);
        if (tig == 0) {
            atomicAdd(&rowsum[wm * 64 + mi * 16 + grp], p0);
            atomicAdd(&rowsum[wm * 64 + mi * 16 + grp + 8], p1);
        }
    }
    __syncthreads();

    // ---- per-node softmax over the 4 paths ----
    int nib = (M - bm) >> 2;
    const int nodes_in_blk = nib < 32 ? nib : 32;
    if (tid < 32 && tid < nodes_in_blk) {
        float l0 = rowsum[tid * 4], l1 = rowsum[tid * 4 + 1];
        float l2 = rowsum[tid * 4 + 2], l3 = rowsum[tid * 4 + 3];
        float m = fmaxf(fmaxf(l0, l1), fmaxf(l2, l3));
        float e0 = __expf(l0 - m), e1 = __expf(l1 - m);
        float e2 = __expf(l2 - m), e3 = __expf(l3 - m);
        float inv = 1.0f / (e0 + e1 + e2 + e3);
        rowsum[tid * 4]     = e0 * inv;
        rowsum[tid * 4 + 1] = e1 * inv;
        rowsum[tid * 4 + 2] = e2 * inv;
        rowsum[tid * 4 + 3] = e3 * inv;
    }
    __syncthreads();

    // ---- combine (vectorized): thread owns 8 dims of one node ----
    // rows bm+nl*4+p; row stride in uint4 units = K/8 = 32.
    const int node0 = bm >> 2;
#pragma unroll
    for (int it = 0; it < 4; it++) {
        int idx = tid + 256 * it;            // 0..1023
        int nl = idx >> 5;                   // node_local 0..31
        int d8 = (idx & 31) * 8;             // dim base
        if (nl >= nodes_in_blk) break;
        const uint4* zr = (const uint4*)(A + (long long)(bm + nl * 4) * K + d8);
        uint4 v0 = zr[0], v1 = zr[32], v2 = zr[64], v3 = zr[96];
        float c0 = rowsum[nl * 4],     c1 = rowsum[nl * 4 + 1];
        float c2 = rowsum[nl * 4 + 2], c3 = rowsum[nl * 4 + 3];
        const __half2* h0 = (const __half2*)&v0;
        const __half2* h1 = (const __half2*)&v1;
        const __half2* h2 = (const __half2*)&v2;
        const __half2* h3 = (const __half2*)&v3;
        float o[8];
#pragma unroll
        for (int j = 0; j < 4; j++) {
            float2 f0 = __half22float2(h0[j]);
            float2 f1 = __half22float2(h1[j]);
            float2 f2 = __half22float2(h2[j]);
            float2 f3 = __half22float2(h3[j]);
            o[2 * j]     = c0 * f0.x + c1 * f1.x + c2 * f2.x + c3 * f3.x;
            o[2 * j + 1] = c0 * f0.y + c1 * f1.y + c2 * f2.y + c3 * f3.y;
        }
        float* op = out + (long long)(node0 + nl) * D + d8;
        *(float4*)op       = make_float4(o[0], o[1], o[2], o[3]);
        *(float4*)(op + 4) = make_float4(o[4], o[5], o[6], o[7]);
    }
}

// ---------------- GCN aggregation pipeline (all 4 paths batched) -----------
__global__ void k_deg_init() {
    int i = blockIdx.x * 256 + threadIdx.x;
    if (i < NG) g_deg[i] = 1;   // self loop
}

__global__ void k_hist(const int* __restrict__ eidx) {
    int e = blockIdx.x * 256 + threadIdx.x;
    if (e < NP * NE) {
        int p = e / NE, i = e - p * NE;
        int dst = eidx[(size_t)p * 2 * NE + NE + i];
        atomicAdd(&g_deg[p * NN + dst], 1);
    }
}

__global__ void k_scan1() {
    __shared__ int red[8];
    int b = blockIdx.x, tid = threadIdx.x;
    int lane = tid & 31, warp = tid >> 5;
    int i0 = b * 512 + tid * 2;
    int s = 0;
    if (i0 < NG)     s += g_deg[i0] - 1;
    if (i0 + 1 < NG) s += g_deg[i0 + 1] - 1;
#pragma unroll
    for (int o = 16; o; o >>= 1) s += __shfl_xor_sync(0xffffffffu, s, o);
    if (lane == 0) red[warp] = s;
    __syncthreads();
    if (tid == 0) {
        int t = 0;
#pragma unroll
        for (int w = 0; w < 8; w++) t += red[w];
        g_part[b] = t;
    }
}

__global__ void k_scan2() {
    __shared__ int s[512];
    int tid = threadIdx.x;
    int v = (tid < SCAN_BLK) ? g_part[tid] : 0;
    s[tid] = v;
    __syncthreads();
    for (int off = 1; off < 512; off <<= 1) {
        int u = (tid >= off) ? s[tid - off] : 0;
        __syncthreads();
        s[tid] += u;
        __syncthreads();
    }
    if (tid < SCAN_BLK) g_part[tid] = s[tid] - v;   // exclusive
}

__global__ void k_scan3() {
    __shared__ int wsum[8];
    int b = blockIdx.x, tid = threadIdx.x;
    int lane = tid & 31, warp = tid >> 5;
    int i0 = b * 512 + tid * 2;
    int d0 = (i0 < NG) ? g_deg[i0] : 1;
    int d1 = (i0 + 1 < NG) ? g_deg[i0 + 1] : 1;
    int v0 = d0 - 1, v1 = d1 - 1;
    int s = v0 + v1;
    int sc = s;
#pragma unroll
    for (int o = 1; o < 32; o <<= 1) {
        int u = __shfl_up_sync(0xffffffffu, sc, o);
        if (lane >= o) sc += u;
    }
    if (lane == 31) wsum[warp] = sc;
    __syncthreads();
    int wbase = 0;
    for (int w = 0; w < warp; w++) wbase += wsum[w];
    int base = g_part[b] + wbase + (sc - s);
    if (i0 < NG) {
        g_rowoff[i0] = base; g_rowcur[i0] = base;
        g_dinv[i0] = rsqrtf((float)d0);
    }
    if (i0 + 1 < NG) {
        g_rowoff[i0 + 1] = base + v0; g_rowcur[i0 + 1] = base + v0;
        g_dinv[i0 + 1] = rsqrtf((float)d1);
    }
    if (b == 0 && tid == 0) g_rowoff[NG] = NP * NE;
}

__global__ void k_fill(const int* __restrict__ eidx) {
    int e = blockIdx.x * 256 + threadIdx.x;
    if (e < NP * NE) {
        int p = e / NE, i = e - p * NE;
        int src = eidx[(size_t)p * 2 * NE + i];
        int dst = eidx[(size_t)p * 2 * NE + NE + i];
        int pos = atomicAdd(&g_rowcur[p * NN + dst], 1);
        g_srcs[pos] = src;
    }
}

// pull: one warp per (path,node); LDG.128 gather, 8-edge unroll, fp32 acc.
// z written INTERLEAVED row (node*4 + p).
__global__ void k_pull(const float* __restrict__ bs) {
    int g = blockIdx.x * 8 + (threadIdx.x >> 5);
    if (g >= NG) return;
    int lane = threadIdx.x & 31;
    int p = g / NN, node = g - p * NN;

    float di = g_dinv[g];
    const uint4* xw = (const uint4*)g_xwh + (size_t)p * (NND / 8);
    float acc[8];
    {
        uint4 v = xw[(size_t)node * 32 + lane];
        const __half2* h = (const __half2*)&v;
        float dd = di * di;
#pragma unroll
        for (int j = 0; j < 4; j++) {
            float2 f = __half22float2(h[j]);
            acc[2 * j]     = dd * f.x;
            acc[2 * j + 1] = dd * f.y;
        }
    }

    int beg = g_rowoff[g];
    int end = g_rowoff[g + 1];
    const float* dv = g_dinv + p * NN;
    int e = beg;
    for (; e + 8 <= end; e += 8) {
        int   si[8];
        float nr[8];
        uint4 vv[8];
#pragma unroll
        for (int q = 0; q < 8; q++) si[q] = g_srcs[e + q];
#pragma unroll
        for (int q = 0; q < 8; q++) nr[q] = di * dv[si[q]];
#pragma unroll
        for (int q = 0; q < 8; q++) vv[q] = xw[(size_t)si[q] * 32 + lane];
#pragma unroll
        for (int j = 0; j < 4; j++) {
#pragma unroll
            for (int q = 0; q < 8; q++) {
                float2 f = __half22float2(((const __half2*)&vv[q])[j]);
                acc[2 * j]     = fmaf(nr[q], f.x, acc[2 * j]);
                acc[2 * j + 1] = fmaf(nr[q], f.y, acc[2 * j + 1]);
            }
        }
    }
    for (; e < end; e++) {
        int s0 = g_srcs[e];
        float n0 = di * dv[s0];
        uint4 v0 = xw[(size_t)s0 * 32 + lane];
        const __half2* h0 = (const __half2*)&v0;
#pragma unroll
        for (int j = 0; j < 4; j++) {
            float2 f0 = __half22float2(h0[j]);
            acc[2 * j]     = fmaf(n0, f0.x, acc[2 * j]);
            acc[2 * j + 1] = fmaf(n0, f0.y, acc[2 * j + 1]);
        }
    }

    // write: lane owns dims [lane*8, lane*8+8)
    int c = lane * 8;
    const float4* bp4 = (const float4*)(bs + p * D + c);
    float4 b0 = bp4[0], b1 = bp4[1];
    uint4 o;
    __half2* oh = (__half2*)&o;
    oh[0] = __floats2half2_rn(acc[0] + b0.x, acc[1] + b0.y);
    oh[1] = __floats2half2_rn(acc[2] + b0.z, acc[3] + b0.w);
    oh[2] = __floats2half2_rn(acc[4] + b1.x, acc[5] + b1.y);
    oh[3] = __floats2half2_rn(acc[6] + b1.z, acc[7] + b1.w);
    ((uint4*)g_zh)[((size_t)node * NP + p) * 32 + lane] = o;
}

// ---------------- launch ----------------------------------------------------
extern "C" void kernel_launch(void* const* d_in, const int* in_sizes, int n_in,
                              void* d_out, int out_size) {
    const float* x    = (const float*)d_in[0];
    const int*   eidx = (const int*)d_in[1];
    const float* Ws   = (const float*)d_in[2];
    const float* bs   = (const float*)d_in[3];
    const float* w1   = (const float*)d_in[4];
    const float* b1   = (const float*)d_in[5];
    const float* w2   = (const float*)d_in[6];
    float* out = (float*)d_out;

    void* p_xh = nullptr; void* p_wsT = nullptr; void* p_w1T = nullptr;
    void* p_xwh = nullptr; void* p_zh = nullptr;
    cudaGetSymbolAddress(&p_xh,  g_xh);
    cudaGetSymbolAddress(&p_wsT, g_wsT);
    cudaGetSymbolAddress(&p_w1T, g_w1T);
    cudaGetSymbolAddress(&p_xwh, g_xwh);
    cudaGetSymbolAddress(&p_zh,  g_zh);

    cudaFuncSetAttribute(k_gemm_xw,
        cudaFuncAttributeMaxDynamicSharedMemorySize, DYNBYTES);
    cudaFuncSetAttribute(k_gemm_attn,
        cudaFuncAttributeMaxDynamicSharedMemorySize, DYNBYTES);

    // one-time side stream + fork/join events (no device memory involved;
    // every call performs the identical launch sequence)
    static cudaStream_t s_side = nullptr;
    static cudaEvent_t  s_fork = nullptr, s_join = nullptr;
    if (s_side == nullptr) {
        cudaStreamCreateWithFlags(&s_side, cudaStreamNonBlocking);
        cudaEventCreateWithFlags(&s_fork, cudaEventDisableTiming);
        cudaEventCreateWithFlags(&s_join, cudaEventDisableTiming);
    }

    // ---- fork: CSR build (depends only on eidx) on side stream ----
    cudaEventRecord(s_fork, 0);
    cudaStreamWaitEvent(s_side, s_fork, 0);
    k_deg_init<<<(NG + 255) / 256, 256, 0, s_side>>>();
    k_hist<<<(NP * NE + 255) / 256, 256, 0, s_side>>>(eidx);
    k_scan1<<<SCAN_BLK, 256, 0, s_side>>>();
    k_scan2<<<1, 512, 0, s_side>>>();
    k_scan3<<<SCAN_BLK, 256, 0, s_side>>>();
    k_fill<<<(NP * NE + 255) / 256, 256, 0, s_side>>>(eidx);
    cudaEventRecord(s_join, s_side);

    // ---- main: fp16 prep + batched feature GEMM ----
    k_cvt_x<<<(NND / 4 + 255) / 256, 256>>>(x);
    k_cvt_wT<<<dim3(D / 32, D / 32, NP), dim3(32, 8)>>>(Ws, (__half*)p_wsT, D, D);
    k_cvt_wT<<<dim3(D / 32, DH / 32, 1), dim3(32, 8)>>>(w1, (__half*)p_w1T, D, DH);
    k_gemm_xw<<<dim3(D / 128, (NN + 127) / 128, NP), 256, DYNBYTES>>>(
        (const __half*)p_xh, (const __half*)p_wsT, (__half*)p_xwh, NN, D,
        (long long)D * D, (long long)NND);

    // ---- join: pull needs both chains ----
    cudaStreamWaitEvent(0, s_join, 0);
    k_pull<<<(NG + 7) / 8, 256>>>(bs);

    // fused: logits + softmax + combine -> out
    k_gemm_attn<<<dim3(1, (NROWS + 127) / 128), 256, DYNBYTES>>>(
        (const __half*)p_zh, (const __half*)p_w1T, b1, w2, out, NROWS);
}